// round 1
// baseline (speedup 1.0000x reference)
#include <cuda_runtime.h>
#include <math.h>
#include <stdint.h>

// Problem dims (fixed by the reference)
#define B_ 4
#define S_ 2048
#define E_ 2048
#define H_ 16
#define D_ 128
#define M_ (B_ * S_)        // 8192 tokens
#define NQKV_ (3 * H_ * D_) // 6144
#define HD_ (H_ * D_)       // 2048

// Scratch (allocation-free rule: __device__ globals)
__device__ float g_qkv[(size_t)M_ * NQKV_]; // 192 MiB: fused qkv GEMM output
__device__ float g_q[(size_t)M_ * HD_];     // 64 MiB: q after rmsnorm+rope
__device__ float g_k[(size_t)M_ * HD_];     // 64 MiB: k after rmsnorm+rope
__device__ float g_o[(size_t)M_ * HD_];     // 64 MiB: attention output

// ---------------------------------------------------------------------------
// Kernel 1/4: fp32 SGEMM, 128x128x16 tile, 256 threads, 8x8 per thread.
// C[M x N] = A[M x K] * B[K x N], all row-major. M fixed at gridDim.y*128.
// ---------------------------------------------------------------------------
__global__ void __launch_bounds__(256) sgemm128(
    const float* __restrict__ A, const float* __restrict__ Bm,
    float* __restrict__ C, int N, int K) {
    __shared__ float As[16][128]; // transposed: As[k][m]
    __shared__ float Bs[16][128]; // Bs[k][n]

    const int tid = threadIdx.x;
    const int tx = tid & 15;       // 0..15 -> col group
    const int ty = tid >> 4;       // 0..15 -> row group
    const int rowBase = blockIdx.y * 128;
    const int colBase = blockIdx.x * 128;

    const int arow = tid >> 2;          // 0..63
    const int acol = (tid & 3) * 4;     // 0,4,8,12
    const int brow = tid >> 5;          // 0..7
    const int bcol = (tid & 31) * 4;    // 0..124

    float acc[8][8];
#pragma unroll
    for (int i = 0; i < 8; i++)
#pragma unroll
        for (int j = 0; j < 8; j++) acc[i][j] = 0.0f;

    for (int k0 = 0; k0 < K; k0 += 16) {
        // Load A tile (128x16), store transposed
#pragma unroll
        for (int rr = 0; rr < 2; rr++) {
            int r = arow + rr * 64;
            float4 a4 = *(const float4*)&A[(size_t)(rowBase + r) * K + k0 + acol];
            As[acol + 0][r] = a4.x;
            As[acol + 1][r] = a4.y;
            As[acol + 2][r] = a4.z;
            As[acol + 3][r] = a4.w;
        }
        // Load B tile (16x128)
#pragma unroll
        for (int rr = 0; rr < 2; rr++) {
            int r = brow + rr * 8;
            float4 b4 = *(const float4*)&Bm[(size_t)(k0 + r) * N + colBase + bcol];
            *(float4*)&Bs[r][bcol] = b4;
        }
        __syncthreads();

#pragma unroll
        for (int kk = 0; kk < 16; kk++) {
            float aR[8], bR[8];
            *(float4*)&aR[0] = *(const float4*)&As[kk][ty * 8];
            *(float4*)&aR[4] = *(const float4*)&As[kk][ty * 8 + 4];
            *(float4*)&bR[0] = *(const float4*)&Bs[kk][tx * 8];
            *(float4*)&bR[4] = *(const float4*)&Bs[kk][tx * 8 + 4];
#pragma unroll
            for (int i = 0; i < 8; i++)
#pragma unroll
                for (int j = 0; j < 8; j++) acc[i][j] += aR[i] * bR[j];
        }
        __syncthreads();
    }

#pragma unroll
    for (int i = 0; i < 8; i++) {
        float* crow = &C[(size_t)(rowBase + ty * 8 + i) * N + colBase + tx * 8];
        *(float4*)&crow[0] = make_float4(acc[i][0], acc[i][1], acc[i][2], acc[i][3]);
        *(float4*)&crow[4] = make_float4(acc[i][4], acc[i][5], acc[i][6], acc[i][7]);
    }
}

// ---------------------------------------------------------------------------
// Kernel 2/4: RMSNorm (eps=0.01) + NeoX RoPE (theta=10000) for q and k.
// One 128-thread block per (token m, head h) row.
// ---------------------------------------------------------------------------
__global__ void __launch_bounds__(128) norm_rope(
    const float* __restrict__ qw, const float* __restrict__ kw) {
    const int m = blockIdx.x >> 4;   // token index (b*S + s)
    const int h = blockIdx.x & 15;
    const int s = m & (S_ - 1);
    const int d = threadIdx.x;

    const size_t base = (size_t)m * NQKV_ + (size_t)h * D_ + d;
    float qv = g_qkv[base];
    float kv = g_qkv[base + HD_];

    float sq = qv * qv, sk = kv * kv;
#pragma unroll
    for (int off = 16; off > 0; off >>= 1) {
        sq += __shfl_xor_sync(0xffffffffu, sq, off);
        sk += __shfl_xor_sync(0xffffffffu, sk, off);
    }
    __shared__ float wq[4], wk[4];
    __shared__ float shq[128], shk[128];
    const int lane = d & 31, w = d >> 5;
    if (lane == 0) { wq[w] = sq; wk[w] = sk; }
    __syncthreads();
    float tq = wq[0] + wq[1] + wq[2] + wq[3];
    float tk = wk[0] + wk[1] + wk[2] + wk[3];
    float rq = rsqrtf(tq * (1.0f / 128.0f) + 0.01f);
    float rk = rsqrtf(tk * (1.0f / 128.0f) + 0.01f);
    shq[d] = qv * rq * qw[d];
    shk[d] = kv * rk * kw[d];
    __syncthreads();

    const int i2 = d & 63;
    float inv = powf(10000.0f, -(float)(2 * i2) * (1.0f / 128.0f));
    float ang = (float)s * inv;
    float sn, cs;
    sincosf(ang, &sn, &cs);
    float rotq = (d < 64) ? -shq[d + 64] : shq[d - 64];
    float rotk = (d < 64) ? -shk[d + 64] : shk[d - 64];

    const size_t ob = (size_t)m * HD_ + (size_t)h * D_ + d;
    g_q[ob] = shq[d] * cs + rotq * sn;
    g_k[ob] = shk[d] * cs + rotk * sn;
}

// ---------------------------------------------------------------------------
// Kernel 3/4: causal flash attention, fp32, BR=BC=64, D=128.
// Block: 256 threads as 16(tx) x 16(ty). Each thread: 4 rows x 4 score cols,
// O accumulator 4 rows x 8 value cols. Online softmax.
// ---------------------------------------------------------------------------
#define BR 64
#define BC 64
#define SQ_STR 129
#define SK_STR 129
#define SV_STR 128
#define SP_STR 65
#define FLASH_SMEM_FLOATS (BR * SQ_STR + BC * SK_STR + BC * SV_STR + BR * SP_STR)
#define FLASH_SMEM_BYTES (FLASH_SMEM_FLOATS * 4)

__global__ void __launch_bounds__(256) flash_attn() {
    extern __shared__ float sm[];
    float* sQ = sm;
    float* sK = sQ + BR * SQ_STR;
    float* sV = sK + BC * SK_STR;
    float* sP = sV + BC * SV_STR;

    const int tid = threadIdx.x;
    const int tx = tid & 15;
    const int ty = tid >> 4;
    const int bh = blockIdx.y;
    const int b = bh >> 4;
    const int h = bh & 15;
    const int iTile = blockIdx.x;
    const int rowBase = iTile * BR;

    const size_t qkbase = (size_t)(b * S_) * HD_ + (size_t)h * D_;
    const size_t vbase = (size_t)(b * S_) * NQKV_ + 2 * HD_ + (size_t)h * D_;

    // Load Q tile
    for (int idx = tid; idx < BR * 32; idx += 256) {
        int r = idx >> 5;
        int c4 = (idx & 31) * 4;
        float4 v = *(const float4*)&g_q[qkbase + (size_t)(rowBase + r) * HD_ + c4];
        sQ[r * SQ_STR + c4 + 0] = v.x;
        sQ[r * SQ_STR + c4 + 1] = v.y;
        sQ[r * SQ_STR + c4 + 2] = v.z;
        sQ[r * SQ_STR + c4 + 3] = v.w;
    }

    float m_i[4], l_i[4], O[4][8];
#pragma unroll
    for (int i = 0; i < 4; i++) {
        m_i[i] = -1e30f;
        l_i[i] = 0.0f;
#pragma unroll
        for (int j = 0; j < 8; j++) O[i][j] = 0.0f;
    }

    const float SCALE = 0.08838834764831845f; // 1/sqrt(128)

    for (int jt = 0; jt <= iTile; jt++) {
        __syncthreads(); // protect sK/sV/sP from previous iteration's readers
        const int jBase = jt * BC;
        for (int idx = tid; idx < BC * 32; idx += 256) {
            int r = idx >> 5;
            int c4 = (idx & 31) * 4;
            float4 kv = *(const float4*)&g_k[qkbase + (size_t)(jBase + r) * HD_ + c4];
            sK[r * SK_STR + c4 + 0] = kv.x;
            sK[r * SK_STR + c4 + 1] = kv.y;
            sK[r * SK_STR + c4 + 2] = kv.z;
            sK[r * SK_STR + c4 + 3] = kv.w;
            float4 vv = *(const float4*)&g_qkv[vbase + (size_t)(jBase + r) * NQKV_ + c4];
            *(float4*)&sV[r * SV_STR + c4] = vv;
        }
        __syncthreads();

        // S = Q K^T (64x64 per tile, 4x4 per thread)
        float sc[4][4];
#pragma unroll
        for (int i = 0; i < 4; i++)
#pragma unroll
            for (int j = 0; j < 4; j++) sc[i][j] = 0.0f;

#pragma unroll 4
        for (int d = 0; d < D_; d++) {
            float a0 = sQ[(ty * 4 + 0) * SQ_STR + d];
            float a1 = sQ[(ty * 4 + 1) * SQ_STR + d];
            float a2 = sQ[(ty * 4 + 2) * SQ_STR + d];
            float a3 = sQ[(ty * 4 + 3) * SQ_STR + d];
            float b0 = sK[(tx * 4 + 0) * SK_STR + d];
            float b1 = sK[(tx * 4 + 1) * SK_STR + d];
            float b2 = sK[(tx * 4 + 2) * SK_STR + d];
            float b3 = sK[(tx * 4 + 3) * SK_STR + d];
            sc[0][0] += a0 * b0; sc[0][1] += a0 * b1; sc[0][2] += a0 * b2; sc[0][3] += a0 * b3;
            sc[1][0] += a1 * b0; sc[1][1] += a1 * b1; sc[1][2] += a1 * b2; sc[1][3] += a1 * b3;
            sc[2][0] += a2 * b0; sc[2][1] += a2 * b1; sc[2][2] += a2 * b2; sc[2][3] += a2 * b3;
            sc[3][0] += a3 * b0; sc[3][1] += a3 * b1; sc[3][2] += a3 * b2; sc[3][3] += a3 * b3;
        }

        // scale + causal mask + online softmax (per row; 16 tx threads redundant)
#pragma unroll
        for (int i = 0; i < 4; i++) {
            const int row = rowBase + ty * 4 + i;
            float tm = -1e30f;
#pragma unroll
            for (int j = 0; j < 4; j++) {
                int col = jBase + tx * 4 + j;
                float v = sc[i][j] * SCALE;
                if (col > row) v = -1e30f;
                sc[i][j] = v;
                tm = fmaxf(tm, v);
            }
#pragma unroll
            for (int off = 8; off > 0; off >>= 1)
                tm = fmaxf(tm, __shfl_xor_sync(0xffffffffu, tm, off));
            float mnew = fmaxf(m_i[i], tm);
            float rs = 0.0f;
#pragma unroll
            for (int j = 0; j < 4; j++) {
                float p = __expf(sc[i][j] - mnew);
                sc[i][j] = p;
                rs += p;
            }
#pragma unroll
            for (int off = 8; off > 0; off >>= 1)
                rs += __shfl_xor_sync(0xffffffffu, rs, off);
            float alpha = __expf(m_i[i] - mnew);
            l_i[i] = l_i[i] * alpha + rs;
            m_i[i] = mnew;
#pragma unroll
            for (int j = 0; j < 8; j++) O[i][j] *= alpha;
            // stash P
#pragma unroll
            for (int j = 0; j < 4; j++)
                sP[(ty * 4 + i) * SP_STR + tx * 4 + j] = sc[i][j];
        }
        __syncthreads();

        // O += P @ V
#pragma unroll 2
        for (int c = 0; c < BC; c++) {
            float p0 = sP[(ty * 4 + 0) * SP_STR + c];
            float p1 = sP[(ty * 4 + 1) * SP_STR + c];
            float p2 = sP[(ty * 4 + 2) * SP_STR + c];
            float p3 = sP[(ty * 4 + 3) * SP_STR + c];
            float4 v0 = *(const float4*)&sV[c * SV_STR + tx * 8];
            float4 v1 = *(const float4*)&sV[c * SV_STR + tx * 8 + 4];
            O[0][0] += p0 * v0.x; O[0][1] += p0 * v0.y; O[0][2] += p0 * v0.z; O[0][3] += p0 * v0.w;
            O[0][4] += p0 * v1.x; O[0][5] += p0 * v1.y; O[0][6] += p0 * v1.z; O[0][7] += p0 * v1.w;
            O[1][0] += p1 * v0.x; O[1][1] += p1 * v0.y; O[1][2] += p1 * v0.z; O[1][3] += p1 * v0.w;
            O[1][4] += p1 * v1.x; O[1][5] += p1 * v1.y; O[1][6] += p1 * v1.z; O[1][7] += p1 * v1.w;
            O[2][0] += p2 * v0.x; O[2][1] += p2 * v0.y; O[2][2] += p2 * v0.z; O[2][3] += p2 * v0.w;
            O[2][4] += p2 * v1.x; O[2][5] += p2 * v1.y; O[2][6] += p2 * v1.z; O[2][7] += p2 * v1.w;
            O[3][0] += p3 * v0.x; O[3][1] += p3 * v0.y; O[3][2] += p3 * v0.z; O[3][3] += p3 * v0.w;
            O[3][4] += p3 * v1.x; O[3][5] += p3 * v1.y; O[3][6] += p3 * v1.z; O[3][7] += p3 * v1.w;
        }
    }

    // normalize + write
#pragma unroll
    for (int i = 0; i < 4; i++) {
        float inv = 1.0f / l_i[i];
        const int r = rowBase + ty * 4 + i;
        float* dst = &g_o[(size_t)(b * S_ + r) * HD_ + (size_t)h * D_ + tx * 8];
        *(float4*)&dst[0] = make_float4(O[i][0] * inv, O[i][1] * inv, O[i][2] * inv, O[i][3] * inv);
        *(float4*)&dst[4] = make_float4(O[i][4] * inv, O[i][5] * inv, O[i][6] * inv, O[i][7] * inv);
    }
}

// ---------------------------------------------------------------------------
// Launcher
// ---------------------------------------------------------------------------
extern "C" void kernel_launch(void* const* d_in, const int* in_sizes, int n_in,
                              void* d_out, int out_size) {
    const float* x = (const float*)d_in[0];      // [B,S,E]
    const float* wqkv = (const float*)d_in[1];   // [E,3,H,D]
    const float* wproj = (const float*)d_in[2];  // [H,D,E]
    const float* qw = (const float*)d_in[3];     // [D]
    const float* kw = (const float*)d_in[4];     // [D]
    float* out = (float*)d_out;                  // [B,S,E]

    void *p_qkv, *p_o;
    cudaGetSymbolAddress(&p_qkv, g_qkv);
    cudaGetSymbolAddress(&p_o, g_o);

    // 1) fused QKV projection: [8192,2048] x [2048,6144]
    sgemm128<<<dim3(NQKV_ / 128, M_ / 128), 256>>>(x, wqkv, (float*)p_qkv, NQKV_, E_);

    // 2) rmsnorm + rope on q and k
    norm_rope<<<M_ * H_, 128>>>(qw, kw);

    // 3) causal flash attention
    cudaFuncSetAttribute(flash_attn, cudaFuncAttributeMaxDynamicSharedMemorySize,
                         FLASH_SMEM_BYTES);
    flash_attn<<<dim3(S_ / BR, B_ * H_), 256, FLASH_SMEM_BYTES>>>();

    // 4) output projection: [8192,2048] x [2048,2048]
    sgemm128<<<dim3(E_ / 128, M_ / 128), 256>>>((const float*)p_o, wproj, out, E_, HD_);
}

// round 3
// speedup vs baseline: 1.5798x; 1.5798x over previous
#include <cuda_runtime.h>
#include <cuda_bf16.h>
#include <math.h>
#include <stdint.h>

// Problem dims (fixed by the reference)
#define B_ 4
#define S_ 2048
#define E_ 2048
#define H_ 16
#define D_ 128
#define M_ (B_ * S_)        // 8192 tokens
#define NQKV_ (3 * H_ * D_) // 6144
#define HD_ (H_ * D_)       // 2048
#define K3_ (3 * E_)        // 6144: concatenated split-bf16 K

// Scratch (allocation-free rule: __device__ globals)
__device__ float g_qkv[(size_t)M_ * NQKV_];           // fused qkv GEMM output
__device__ float g_q[(size_t)M_ * HD_];               // q after rmsnorm+rope
__device__ float g_k[(size_t)M_ * HD_];               // k after rmsnorm+rope
__device__ float g_o[(size_t)M_ * HD_];               // attention output
__device__ __nv_bfloat16 g_as[(size_t)M_ * K3_];      // A' = [hi | lo | hi]
__device__ __nv_bfloat16 g_bs[(size_t)NQKV_ * K3_];   // B'^T = [hi | hi | lo]

// ---------------------------------------------------------------------------
// Helpers
// ---------------------------------------------------------------------------
__device__ __forceinline__ uint32_t smem_u32(const void* p) {
    uint32_t a;
    asm("{ .reg .u64 t; cvta.to.shared.u64 t, %1; cvt.u32.u64 %0, t; }"
        : "=r"(a) : "l"(p));
    return a;
}
__device__ __forceinline__ void cp16(uint32_t s, const void* g) {
    asm volatile("cp.async.cg.shared.global [%0], [%1], 16;\n" :: "r"(s), "l"(g));
}
__device__ __forceinline__ void cp_commit() {
    asm volatile("cp.async.commit_group;\n" ::: "memory");
}
template <int N>
__device__ __forceinline__ void cp_wait() {
    asm volatile("cp.async.wait_group %0;\n" :: "n"(N) : "memory");
}
__device__ __forceinline__ void ldmx4(uint32_t a, uint32_t& r0, uint32_t& r1,
                                      uint32_t& r2, uint32_t& r3) {
    asm volatile("ldmatrix.sync.aligned.m8n8.x4.shared.b16 {%0,%1,%2,%3}, [%4];"
                 : "=r"(r0), "=r"(r1), "=r"(r2), "=r"(r3) : "r"(a));
}
__device__ __forceinline__ void mma16816(float* c, uint32_t a0, uint32_t a1,
                                         uint32_t a2, uint32_t a3, uint32_t b0,
                                         uint32_t b1) {
    asm volatile(
        "mma.sync.aligned.m16n8k16.row.col.f32.bf16.bf16.f32 "
        "{%0,%1,%2,%3}, {%4,%5,%6,%7}, {%8,%9}, {%0,%1,%2,%3};"
        : "+f"(c[0]), "+f"(c[1]), "+f"(c[2]), "+f"(c[3])
        : "r"(a0), "r"(a1), "r"(a2), "r"(a3), "r"(b0), "r"(b1));
}

// ---------------------------------------------------------------------------
// Split kernels: fp32 -> concatenated split-bf16 operands.
// A' row (stride 3K): [hi(0:K) | lo(0:K) | hi(0:K)]
// B'^T row (stride 3K): [hi(0:K) | hi(0:K) | lo(0:K)]  (from B[K,N])
// ---------------------------------------------------------------------------
__global__ void __launch_bounds__(256) splitA(
    const float* __restrict__ X, __nv_bfloat16* __restrict__ Y, int K) {
    int i4 = (blockIdx.x * 256 + threadIdx.x) * 4;
    int m = i4 / K;
    int k = i4 % K;
    float4 v = *(const float4*)&X[i4];
    __nv_bfloat16 h[4], l[4];
    float f[4] = {v.x, v.y, v.z, v.w};
#pragma unroll
    for (int j = 0; j < 4; j++) {
        h[j] = __float2bfloat16(f[j]);
        l[j] = __float2bfloat16(f[j] - __bfloat162float(h[j]));
    }
    __nv_bfloat162 hp0 = __halves2bfloat162(h[0], h[1]);
    __nv_bfloat162 hp1 = __halves2bfloat162(h[2], h[3]);
    __nv_bfloat162 lp0 = __halves2bfloat162(l[0], l[1]);
    __nv_bfloat162 lp1 = __halves2bfloat162(l[2], l[3]);
    size_t base = (size_t)m * (3 * K) + k;
    __nv_bfloat162* p0 = (__nv_bfloat162*)&Y[base];
    __nv_bfloat162* p1 = (__nv_bfloat162*)&Y[base + K];
    __nv_bfloat162* p2 = (__nv_bfloat162*)&Y[base + 2 * K];
    p0[0] = hp0; p0[1] = hp1;
    p1[0] = lp0; p1[1] = lp1;
    p2[0] = hp0; p2[1] = hp1;
}

__global__ void __launch_bounds__(256) splitTB(
    const float* __restrict__ B, __nv_bfloat16* __restrict__ Y, int K, int N) {
    __shared__ float t[32][33];
    const int k0 = blockIdx.y * 32, n0 = blockIdx.x * 32;
    const int tx = threadIdx.x, ty = threadIdx.y; // 32 x 8
#pragma unroll
    for (int i = 0; i < 32; i += 8)
        t[ty + i][tx] = B[(size_t)(k0 + ty + i) * N + n0 + tx];
    __syncthreads();
#pragma unroll
    for (int i = 0; i < 32; i += 8) {
        float v = t[tx][ty + i]; // B[k0+tx][n0+ty+i]
        __nv_bfloat16 h = __float2bfloat16(v);
        __nv_bfloat16 l = __float2bfloat16(v - __bfloat162float(h));
        size_t base = (size_t)(n0 + ty + i) * (3 * K) + k0 + tx;
        Y[base] = h;
        Y[base + K] = h;
        Y[base + 2 * K] = l;
    }
}

// ---------------------------------------------------------------------------
// HMMA bf16 GEMM: C[M,N] = A'[M,K3] * B't[N,K3]^T, fp32 accumulate.
// 128x128x32 tiles, 3-stage cp.async pipeline, 8 warps (32x64 warp tiles).
// smem rows padded to 80B -> ldmatrix conflict-free.
// ---------------------------------------------------------------------------
#define BM 128
#define BN 128
#define BK 32
#define ROWB 80                       // 64B data + 16B pad
#define STAGE_B (2 * BM * ROWB)       // A tile + B tile = 20480
#define STAGES 3
#define GEMM_SMEM (STAGES * STAGE_B)  // 61440

__global__ void __launch_bounds__(256) hgemm_bf16(
    const __nv_bfloat16* __restrict__ A, const __nv_bfloat16* __restrict__ Bt,
    float* __restrict__ C, int N, int K3) {
    extern __shared__ char smem[];
    const uint32_t sb = smem_u32(smem);
    const int tid = threadIdx.x;
    const int wid = tid >> 5;
    const int lane = tid & 31;
    const int rowBase = blockIdx.y * BM;
    const int colBase = blockIdx.x * BN;
    const int wm = wid & 3;   // M warp group (32 rows)
    const int wn = wid >> 2;  // N warp group (64 cols)
    const int NC = K3 / BK;

    // loader mapping: each thread does 2 rows of A and 2 rows of B, 16B each
    const int lr = tid >> 2;             // 0..63
    const int lcb = (tid & 3) * 16;      // byte offset within 64B row data
    const int lce = (tid & 3) * 8;       // element offset

    auto load_chunk = [&](int ck, int stage) {
        const int k0 = ck * BK;
        const uint32_t sa = sb + stage * STAGE_B;
        const uint32_t sbB = sa + BM * ROWB;
#pragma unroll
        for (int rr = 0; rr < 2; rr++) {
            int r = lr + rr * 64;
            cp16(sa + r * ROWB + lcb, A + (size_t)(rowBase + r) * K3 + k0 + lce);
            cp16(sbB + r * ROWB + lcb, Bt + (size_t)(colBase + r) * K3 + k0 + lce);
        }
        cp_commit();
    };

    load_chunk(0, 0);
    load_chunk(1, 1);

    float acc[2][8][4];
#pragma unroll
    for (int i = 0; i < 2; i++)
#pragma unroll
        for (int j = 0; j < 8; j++)
#pragma unroll
            for (int q = 0; q < 4; q++) acc[i][j][q] = 0.0f;

    // per-lane ldmatrix base offsets (within a stage)
    // A: tile mt, kstep ks: row = wm*32 + mt*16 + (lane&15); col byte = ks*32 + (lane>>4)*16
    const uint32_t aRow = (uint32_t)(wm * 32 + (lane & 15));
    const uint32_t aCol = (uint32_t)((lane >> 4) * 16);
    // B: tile-pair nt, kstep ks: row = wn*64 + nt*16 + (lane&7) + ((lane>>4)&1)*8
    //    col byte = ks*32 + ((lane>>3)&1)*16
    const uint32_t bRow = (uint32_t)(wn * 64 + (lane & 7) + ((lane >> 4) & 1) * 8);
    const uint32_t bCol = (uint32_t)(((lane >> 3) & 1) * 16);

    for (int ck = 0; ck < NC; ck++) {
        if (ck == NC - 1) cp_wait<0>(); else cp_wait<1>();
        __syncthreads();
        if (ck + 2 < NC) load_chunk(ck + 2, (ck + 2) % STAGES);

        const int stage = ck % STAGES;
        const uint32_t sa = sb + stage * STAGE_B;
        const uint32_t sbB = sa + BM * ROWB;

#pragma unroll
        for (int ks = 0; ks < 2; ks++) {
            uint32_t a[2][4];
#pragma unroll
            for (int mt = 0; mt < 2; mt++)
                ldmx4(sa + (aRow + mt * 16) * ROWB + ks * 32 + aCol,
                      a[mt][0], a[mt][1], a[mt][2], a[mt][3]);
            uint32_t b[8][2];
#pragma unroll
            for (int nt = 0; nt < 4; nt++) {
                uint32_t r0, r1, r2, r3;
                ldmx4(sbB + (bRow + nt * 16) * ROWB + ks * 32 + bCol, r0, r1, r2, r3);
                b[nt * 2][0] = r0; b[nt * 2][1] = r1;
                b[nt * 2 + 1][0] = r2; b[nt * 2 + 1][1] = r3;
            }
#pragma unroll
            for (int mt = 0; mt < 2; mt++)
#pragma unroll
                for (int nt = 0; nt < 8; nt++)
                    mma16816(acc[mt][nt], a[mt][0], a[mt][1], a[mt][2], a[mt][3],
                             b[nt][0], b[nt][1]);
        }
    }

    // epilogue: direct global stores
#pragma unroll
    for (int mt = 0; mt < 2; mt++) {
        const int row0 = rowBase + wm * 32 + mt * 16 + lane / 4;
#pragma unroll
        for (int nt = 0; nt < 8; nt++) {
            const int col = colBase + wn * 64 + nt * 8 + (lane & 3) * 2;
            float2* p0 = (float2*)&C[(size_t)row0 * N + col];
            float2* p1 = (float2*)&C[(size_t)(row0 + 8) * N + col];
            *p0 = make_float2(acc[mt][nt][0], acc[mt][nt][1]);
            *p1 = make_float2(acc[mt][nt][2], acc[mt][nt][3]);
        }
    }
}

// ---------------------------------------------------------------------------
// RMSNorm (eps=0.01) + NeoX RoPE (theta=10000) for q and k.
// ---------------------------------------------------------------------------
__global__ void __launch_bounds__(128) norm_rope(
    const float* __restrict__ qw, const float* __restrict__ kw) {
    const int m = blockIdx.x >> 4;
    const int h = blockIdx.x & 15;
    const int s = m & (S_ - 1);
    const int d = threadIdx.x;

    const size_t base = (size_t)m * NQKV_ + (size_t)h * D_ + d;
    float qv = g_qkv[base];
    float kv = g_qkv[base + HD_];

    float sq = qv * qv, sk = kv * kv;
#pragma unroll
    for (int off = 16; off > 0; off >>= 1) {
        sq += __shfl_xor_sync(0xffffffffu, sq, off);
        sk += __shfl_xor_sync(0xffffffffu, sk, off);
    }
    __shared__ float wq[4], wk[4];
    __shared__ float shq[128], shk[128];
    const int lane = d & 31, w = d >> 5;
    if (lane == 0) { wq[w] = sq; wk[w] = sk; }
    __syncthreads();
    float tq = wq[0] + wq[1] + wq[2] + wq[3];
    float tk = wk[0] + wk[1] + wk[2] + wk[3];
    float rq = rsqrtf(tq * (1.0f / 128.0f) + 0.01f);
    float rk = rsqrtf(tk * (1.0f / 128.0f) + 0.01f);
    shq[d] = qv * rq * qw[d];
    shk[d] = kv * rk * kw[d];
    __syncthreads();

    const int i2 = d & 63;
    float inv = powf(10000.0f, -(float)(2 * i2) * (1.0f / 128.0f));
    float ang = (float)s * inv;
    float sn, cs;
    sincosf(ang, &sn, &cs);
    float rotq = (d < 64) ? -shq[d + 64] : shq[d - 64];
    float rotk = (d < 64) ? -shk[d + 64] : shk[d - 64];

    const size_t ob = (size_t)m * HD_ + (size_t)h * D_ + d;
    g_q[ob] = shq[d] * cs + rotq * sn;
    g_k[ob] = shk[d] * cs + rotk * sn;
}

// ---------------------------------------------------------------------------
// Causal flash attention, fp32, BR=BC=64, D=128 (unchanged from round 1).
// ---------------------------------------------------------------------------
#define BR 64
#define BC 64
#define SQ_STR 129
#define SK_STR 129
#define SV_STR 128
#define SP_STR 65
#define FLASH_SMEM_FLOATS (BR * SQ_STR + BC * SK_STR + BC * SV_STR + BR * SP_STR)
#define FLASH_SMEM_BYTES (FLASH_SMEM_FLOATS * 4)

__global__ void __launch_bounds__(256) flash_attn() {
    extern __shared__ float sm[];
    float* sQ = sm;
    float* sK = sQ + BR * SQ_STR;
    float* sV = sK + BC * SK_STR;
    float* sP = sV + BC * SV_STR;

    const int tid = threadIdx.x;
    const int tx = tid & 15;
    const int ty = tid >> 4;
    const int bh = blockIdx.y;
    const int b = bh >> 4;
    const int h = bh & 15;
    const int iTile = blockIdx.x;
    const int rowBase = iTile * BR;

    const size_t qkbase = (size_t)(b * S_) * HD_ + (size_t)h * D_;
    const size_t vbase = (size_t)(b * S_) * NQKV_ + 2 * HD_ + (size_t)h * D_;

    for (int idx = tid; idx < BR * 32; idx += 256) {
        int r = idx >> 5;
        int c4 = (idx & 31) * 4;
        float4 v = *(const float4*)&g_q[qkbase + (size_t)(rowBase + r) * HD_ + c4];
        sQ[r * SQ_STR + c4 + 0] = v.x;
        sQ[r * SQ_STR + c4 + 1] = v.y;
        sQ[r * SQ_STR + c4 + 2] = v.z;
        sQ[r * SQ_STR + c4 + 3] = v.w;
    }

    float m_i[4], l_i[4], O[4][8];
#pragma unroll
    for (int i = 0; i < 4; i++) {
        m_i[i] = -1e30f;
        l_i[i] = 0.0f;
#pragma unroll
        for (int j = 0; j < 8; j++) O[i][j] = 0.0f;
    }

    const float SCALE = 0.08838834764831845f;

    for (int jt = 0; jt <= iTile; jt++) {
        __syncthreads();
        const int jBase = jt * BC;
        for (int idx = tid; idx < BC * 32; idx += 256) {
            int r = idx >> 5;
            int c4 = (idx & 31) * 4;
            float4 kv = *(const float4*)&g_k[qkbase + (size_t)(jBase + r) * HD_ + c4];
            sK[r * SK_STR + c4 + 0] = kv.x;
            sK[r * SK_STR + c4 + 1] = kv.y;
            sK[r * SK_STR + c4 + 2] = kv.z;
            sK[r * SK_STR + c4 + 3] = kv.w;
            float4 vv = *(const float4*)&g_qkv[vbase + (size_t)(jBase + r) * NQKV_ + c4];
            *(float4*)&sV[r * SV_STR + c4] = vv;
        }
        __syncthreads();

        float sc[4][4];
#pragma unroll
        for (int i = 0; i < 4; i++)
#pragma unroll
            for (int j = 0; j < 4; j++) sc[i][j] = 0.0f;

#pragma unroll 4
        for (int d = 0; d < D_; d++) {
            float a0 = sQ[(ty * 4 + 0) * SQ_STR + d];
            float a1 = sQ[(ty * 4 + 1) * SQ_STR + d];
            float a2 = sQ[(ty * 4 + 2) * SQ_STR + d];
            float a3 = sQ[(ty * 4 + 3) * SQ_STR + d];
            float b0 = sK[(tx * 4 + 0) * SK_STR + d];
            float b1 = sK[(tx * 4 + 1) * SK_STR + d];
            float b2 = sK[(tx * 4 + 2) * SK_STR + d];
            float b3 = sK[(tx * 4 + 3) * SK_STR + d];
            sc[0][0] += a0 * b0; sc[0][1] += a0 * b1; sc[0][2] += a0 * b2; sc[0][3] += a0 * b3;
            sc[1][0] += a1 * b0; sc[1][1] += a1 * b1; sc[1][2] += a1 * b2; sc[1][3] += a1 * b3;
            sc[2][0] += a2 * b0; sc[2][1] += a2 * b1; sc[2][2] += a2 * b2; sc[2][3] += a2 * b3;
            sc[3][0] += a3 * b0; sc[3][1] += a3 * b1; sc[3][2] += a3 * b2; sc[3][3] += a3 * b3;
        }

#pragma unroll
        for (int i = 0; i < 4; i++) {
            const int row = rowBase + ty * 4 + i;
            float tm = -1e30f;
#pragma unroll
            for (int j = 0; j < 4; j++) {
                int col = jBase + tx * 4 + j;
                float v = sc[i][j] * SCALE;
                if (col > row) v = -1e30f;
                sc[i][j] = v;
                tm = fmaxf(tm, v);
            }
#pragma unroll
            for (int off = 8; off > 0; off >>= 1)
                tm = fmaxf(tm, __shfl_xor_sync(0xffffffffu, tm, off));
            float mnew = fmaxf(m_i[i], tm);
            float rs = 0.0f;
#pragma unroll
            for (int j = 0; j < 4; j++) {
                float p = __expf(sc[i][j] - mnew);
                sc[i][j] = p;
                rs += p;
            }
#pragma unroll
            for (int off = 8; off > 0; off >>= 1)
                rs += __shfl_xor_sync(0xffffffffu, rs, off);
            float alpha = __expf(m_i[i] - mnew);
            l_i[i] = l_i[i] * alpha + rs;
            m_i[i] = mnew;
#pragma unroll
            for (int j = 0; j < 8; j++) O[i][j] *= alpha;
#pragma unroll
            for (int j = 0; j < 4; j++)
                sP[(ty * 4 + i) * SP_STR + tx * 4 + j] = sc[i][j];
        }
        __syncthreads();

#pragma unroll 2
        for (int c = 0; c < BC; c++) {
            float p0 = sP[(ty * 4 + 0) * SP_STR + c];
            float p1 = sP[(ty * 4 + 1) * SP_STR + c];
            float p2 = sP[(ty * 4 + 2) * SP_STR + c];
            float p3 = sP[(ty * 4 + 3) * SP_STR + c];
            float4 v0 = *(const float4*)&sV[c * SV_STR + tx * 8];
            float4 v1 = *(const float4*)&sV[c * SV_STR + tx * 8 + 4];
            O[0][0] += p0 * v0.x; O[0][1] += p0 * v0.y; O[0][2] += p0 * v0.z; O[0][3] += p0 * v0.w;
            O[0][4] += p0 * v1.x; O[0][5] += p0 * v1.y; O[0][6] += p0 * v1.z; O[0][7] += p0 * v1.w;
            O[1][0] += p1 * v0.x; O[1][1] += p1 * v0.y; O[1][2] += p1 * v0.z; O[1][3] += p1 * v0.w;
            O[1][4] += p1 * v1.x; O[1][5] += p1 * v1.y; O[1][6] += p1 * v1.z; O[1][7] += p1 * v1.w;
            O[2][0] += p2 * v0.x; O[2][1] += p2 * v0.y; O[2][2] += p2 * v0.z; O[2][3] += p2 * v0.w;
            O[2][4] += p2 * v1.x; O[2][5] += p2 * v1.y; O[2][6] += p2 * v1.z; O[2][7] += p2 * v1.w;
            O[3][0] += p3 * v0.x; O[3][1] += p3 * v0.y; O[3][2] += p3 * v0.z; O[3][3] += p3 * v0.w;
            O[3][4] += p3 * v1.x; O[3][5] += p3 * v1.y; O[3][6] += p3 * v1.z; O[3][7] += p3 * v1.w;
        }
    }

#pragma unroll
    for (int i = 0; i < 4; i++) {
        float inv = 1.0f / l_i[i];
        const int r = rowBase + ty * 4 + i;
        float* dst = &g_o[(size_t)(b * S_ + r) * HD_ + (size_t)h * D_ + tx * 8];
        *(float4*)&dst[0] = make_float4(O[i][0] * inv, O[i][1] * inv, O[i][2] * inv, O[i][3] * inv);
        *(float4*)&dst[4] = make_float4(O[i][4] * inv, O[i][5] * inv, O[i][6] * inv, O[i][7] * inv);
    }
}

// ---------------------------------------------------------------------------
// Launcher
// ---------------------------------------------------------------------------
extern "C" void kernel_launch(void* const* d_in, const int* in_sizes, int n_in,
                              void* d_out, int out_size) {
    const float* x = (const float*)d_in[0];      // [B,S,E]
    const float* wqkv = (const float*)d_in[1];   // [E,3,H,D] = [2048,6144]
    const float* wproj = (const float*)d_in[2];  // [H,D,E]   = [2048,2048]
    const float* qw = (const float*)d_in[3];
    const float* kw = (const float*)d_in[4];
    float* out = (float*)d_out;

    void *p_qkv, *p_o, *p_as, *p_bs;
    cudaGetSymbolAddress(&p_qkv, g_qkv);
    cudaGetSymbolAddress(&p_o, g_o);
    cudaGetSymbolAddress(&p_as, g_as);
    cudaGetSymbolAddress(&p_bs, g_bs);

    cudaFuncSetAttribute(hgemm_bf16, cudaFuncAttributeMaxDynamicSharedMemorySize,
                         GEMM_SMEM);
    cudaFuncSetAttribute(flash_attn, cudaFuncAttributeMaxDynamicSharedMemorySize,
                         FLASH_SMEM_BYTES);

    // 1) QKV projection on HMMA tensor cores
    splitA<<<(M_ * E_) / 1024, 256>>>(x, (__nv_bfloat16*)p_as, E_);
    splitTB<<<dim3(NQKV_ / 32, E_ / 32), dim3(32, 8)>>>(
        wqkv, (__nv_bfloat16*)p_bs, E_, NQKV_);
    hgemm_bf16<<<dim3(NQKV_ / BN, M_ / BM), 256, GEMM_SMEM>>>(
        (const __nv_bfloat16*)p_as, (const __nv_bfloat16*)p_bs,
        (float*)p_qkv, NQKV_, K3_);

    // 2) rmsnorm + rope
    norm_rope<<<M_ * H_, 128>>>(qw, kw);

    // 3) causal flash attention (fp32 SIMT)
    flash_attn<<<dim3(S_ / BR, B_ * H_), 256, FLASH_SMEM_BYTES>>>();

    // 4) output projection on HMMA tensor cores
    splitA<<<(M_ * HD_) / 1024, 256>>>((const float*)p_o, (__nv_bfloat16*)p_as, HD_);
    splitTB<<<dim3(E_ / 32, HD_ / 32), dim3(32, 8)>>>(
        wproj, (__nv_bfloat16*)p_bs, HD_, E_);
    hgemm_bf16<<<dim3(E_ / BN, M_ / BM), 256, GEMM_SMEM>>>(
        (const __nv_bfloat16*)p_as, (const __nv_bfloat16*)p_bs,
        out, E_, K3_);
}

// round 4
// speedup vs baseline: 2.5409x; 1.6084x over previous
#include <cuda_runtime.h>
#include <cuda_bf16.h>
#include <math.h>
#include <stdint.h>

// Problem dims (fixed by the reference)
#define B_ 4
#define S_ 2048
#define E_ 2048
#define H_ 16
#define D_ 128
#define M_ (B_ * S_)        // 8192 tokens
#define NQKV_ (3 * H_ * D_) // 6144
#define HD_ (H_ * D_)       // 2048
#define K3_ (3 * E_)        // 6144: concatenated split-bf16 K

// Scratch (allocation-free rule: __device__ globals)
__device__ float g_qkv[(size_t)M_ * NQKV_];           // fused qkv GEMM output
__device__ __nv_bfloat16 g_as[(size_t)M_ * K3_];      // A' = [hi | lo | hi]
__device__ __nv_bfloat16 g_bs[(size_t)NQKV_ * K3_];   // B'^T = [hi | hi | lo]
__device__ __nv_bfloat16 g_qhi[(size_t)M_ * HD_];     // q (scaled) hi
__device__ __nv_bfloat16 g_qlo[(size_t)M_ * HD_];
__device__ __nv_bfloat16 g_khi[(size_t)M_ * HD_];
__device__ __nv_bfloat16 g_klo[(size_t)M_ * HD_];
__device__ __nv_bfloat16 g_vhi[(size_t)M_ * HD_];
__device__ __nv_bfloat16 g_vlo[(size_t)M_ * HD_];

// ---------------------------------------------------------------------------
// Helpers
// ---------------------------------------------------------------------------
__device__ __forceinline__ uint32_t smem_u32(const void* p) {
    uint32_t a;
    asm("{ .reg .u64 t; cvta.to.shared.u64 t, %1; cvt.u32.u64 %0, t; }"
        : "=r"(a) : "l"(p));
    return a;
}
__device__ __forceinline__ void cp16(uint32_t s, const void* g) {
    asm volatile("cp.async.cg.shared.global [%0], [%1], 16;\n" :: "r"(s), "l"(g));
}
__device__ __forceinline__ void cp_commit() {
    asm volatile("cp.async.commit_group;\n" ::: "memory");
}
template <int N>
__device__ __forceinline__ void cp_wait() {
    asm volatile("cp.async.wait_group %0;\n" :: "n"(N) : "memory");
}
__device__ __forceinline__ void ldmx4(uint32_t a, uint32_t& r0, uint32_t& r1,
                                      uint32_t& r2, uint32_t& r3) {
    asm volatile("ldmatrix.sync.aligned.m8n8.x4.shared.b16 {%0,%1,%2,%3}, [%4];"
                 : "=r"(r0), "=r"(r1), "=r"(r2), "=r"(r3) : "r"(a));
}
__device__ __forceinline__ void ldmx4t(uint32_t a, uint32_t& r0, uint32_t& r1,
                                       uint32_t& r2, uint32_t& r3) {
    asm volatile("ldmatrix.sync.aligned.m8n8.x4.trans.shared.b16 {%0,%1,%2,%3}, [%4];"
                 : "=r"(r0), "=r"(r1), "=r"(r2), "=r"(r3) : "r"(a));
}
__device__ __forceinline__ void mma16816(float* c, uint32_t a0, uint32_t a1,
                                         uint32_t a2, uint32_t a3, uint32_t b0,
                                         uint32_t b1) {
    asm volatile(
        "mma.sync.aligned.m16n8k16.row.col.f32.bf16.bf16.f32 "
        "{%0,%1,%2,%3}, {%4,%5,%6,%7}, {%8,%9}, {%0,%1,%2,%3};"
        : "+f"(c[0]), "+f"(c[1]), "+f"(c[2]), "+f"(c[3])
        : "r"(a0), "r"(a1), "r"(a2), "r"(a3), "r"(b0), "r"(b1));
}
__device__ __forceinline__ uint32_t packbf2(float x, float y) {
    __nv_bfloat162 t = __floats2bfloat162_rn(x, y);
    return *(uint32_t*)&t;
}

// ---------------------------------------------------------------------------
// Split kernels: fp32 -> concatenated split-bf16 operands.
// ---------------------------------------------------------------------------
__global__ void __launch_bounds__(256) splitA(
    const float* __restrict__ X, __nv_bfloat16* __restrict__ Y, int K) {
    int i4 = (blockIdx.x * 256 + threadIdx.x) * 4;
    int m = i4 / K;
    int k = i4 % K;
    float4 v = *(const float4*)&X[i4];
    __nv_bfloat16 h[4], l[4];
    float f[4] = {v.x, v.y, v.z, v.w};
#pragma unroll
    for (int j = 0; j < 4; j++) {
        h[j] = __float2bfloat16(f[j]);
        l[j] = __float2bfloat16(f[j] - __bfloat162float(h[j]));
    }
    __nv_bfloat162 hp0 = __halves2bfloat162(h[0], h[1]);
    __nv_bfloat162 hp1 = __halves2bfloat162(h[2], h[3]);
    __nv_bfloat162 lp0 = __halves2bfloat162(l[0], l[1]);
    __nv_bfloat162 lp1 = __halves2bfloat162(l[2], l[3]);
    size_t base = (size_t)m * (3 * K) + k;
    __nv_bfloat162* p0 = (__nv_bfloat162*)&Y[base];
    __nv_bfloat162* p1 = (__nv_bfloat162*)&Y[base + K];
    __nv_bfloat162* p2 = (__nv_bfloat162*)&Y[base + 2 * K];
    p0[0] = hp0; p0[1] = hp1;
    p1[0] = lp0; p1[1] = lp1;
    p2[0] = hp0; p2[1] = hp1;
}

__global__ void __launch_bounds__(256) splitTB(
    const float* __restrict__ B, __nv_bfloat16* __restrict__ Y, int K, int N) {
    __shared__ float t[32][33];
    const int k0 = blockIdx.y * 32, n0 = blockIdx.x * 32;
    const int tx = threadIdx.x, ty = threadIdx.y; // 32 x 8
#pragma unroll
    for (int i = 0; i < 32; i += 8)
        t[ty + i][tx] = B[(size_t)(k0 + ty + i) * N + n0 + tx];
    __syncthreads();
#pragma unroll
    for (int i = 0; i < 32; i += 8) {
        float v = t[tx][ty + i];
        __nv_bfloat16 h = __float2bfloat16(v);
        __nv_bfloat16 l = __float2bfloat16(v - __bfloat162float(h));
        size_t base = (size_t)(n0 + ty + i) * (3 * K) + k0 + tx;
        Y[base] = h;
        Y[base + K] = h;
        Y[base + 2 * K] = l;
    }
}

// V region of g_qkv -> split bf16 hi/lo [M, HD]
__global__ void __launch_bounds__(256) splitV() {
    int i4 = (blockIdx.x * 256 + threadIdx.x) * 4;
    int m = i4 / HD_;
    int j = i4 % HD_;
    float4 v = *(const float4*)&g_qkv[(size_t)m * NQKV_ + 2 * HD_ + j];
    float f[4] = {v.x, v.y, v.z, v.w};
    __nv_bfloat16 h[4], l[4];
#pragma unroll
    for (int q = 0; q < 4; q++) {
        h[q] = __float2bfloat16(f[q]);
        l[q] = __float2bfloat16(f[q] - __bfloat162float(h[q]));
    }
    size_t o = (size_t)m * HD_ + j;
    *(__nv_bfloat162*)&g_vhi[o] = __halves2bfloat162(h[0], h[1]);
    *(__nv_bfloat162*)&g_vhi[o + 2] = __halves2bfloat162(h[2], h[3]);
    *(__nv_bfloat162*)&g_vlo[o] = __halves2bfloat162(l[0], l[1]);
    *(__nv_bfloat162*)&g_vlo[o + 2] = __halves2bfloat162(l[2], l[3]);
}

// ---------------------------------------------------------------------------
// HMMA bf16 GEMM (unchanged from round 3)
// ---------------------------------------------------------------------------
#define BM 128
#define BN 128
#define BK 32
#define ROWB 80
#define STAGE_B (2 * BM * ROWB)
#define STAGES 3
#define GEMM_SMEM (STAGES * STAGE_B)

__global__ void __launch_bounds__(256) hgemm_bf16(
    const __nv_bfloat16* __restrict__ A, const __nv_bfloat16* __restrict__ Bt,
    float* __restrict__ C, int N, int K3) {
    extern __shared__ char smem[];
    const uint32_t sb = smem_u32(smem);
    const int tid = threadIdx.x;
    const int wid = tid >> 5;
    const int lane = tid & 31;
    const int rowBase = blockIdx.y * BM;
    const int colBase = blockIdx.x * BN;
    const int wm = wid & 3;
    const int wn = wid >> 2;
    const int NC = K3 / BK;

    const int lr = tid >> 2;
    const int lcb = (tid & 3) * 16;
    const int lce = (tid & 3) * 8;

    auto load_chunk = [&](int ck, int stage) {
        const int k0 = ck * BK;
        const uint32_t sa = sb + stage * STAGE_B;
        const uint32_t sbB = sa + BM * ROWB;
#pragma unroll
        for (int rr = 0; rr < 2; rr++) {
            int r = lr + rr * 64;
            cp16(sa + r * ROWB + lcb, A + (size_t)(rowBase + r) * K3 + k0 + lce);
            cp16(sbB + r * ROWB + lcb, Bt + (size_t)(colBase + r) * K3 + k0 + lce);
        }
        cp_commit();
    };

    load_chunk(0, 0);
    load_chunk(1, 1);

    float acc[2][8][4];
#pragma unroll
    for (int i = 0; i < 2; i++)
#pragma unroll
        for (int j = 0; j < 8; j++)
#pragma unroll
            for (int q = 0; q < 4; q++) acc[i][j][q] = 0.0f;

    const uint32_t aRow = (uint32_t)(wm * 32 + (lane & 15));
    const uint32_t aCol = (uint32_t)((lane >> 4) * 16);
    const uint32_t bRow = (uint32_t)(wn * 64 + (lane & 7) + ((lane >> 4) & 1) * 8);
    const uint32_t bCol = (uint32_t)(((lane >> 3) & 1) * 16);

    for (int ck = 0; ck < NC; ck++) {
        if (ck == NC - 1) cp_wait<0>(); else cp_wait<1>();
        __syncthreads();
        if (ck + 2 < NC) load_chunk(ck + 2, (ck + 2) % STAGES);

        const int stage = ck % STAGES;
        const uint32_t sa = sb + stage * STAGE_B;
        const uint32_t sbB = sa + BM * ROWB;

#pragma unroll
        for (int ks = 0; ks < 2; ks++) {
            uint32_t a[2][4];
#pragma unroll
            for (int mt = 0; mt < 2; mt++)
                ldmx4(sa + (aRow + mt * 16) * ROWB + ks * 32 + aCol,
                      a[mt][0], a[mt][1], a[mt][2], a[mt][3]);
            uint32_t b[8][2];
#pragma unroll
            for (int nt = 0; nt < 4; nt++) {
                uint32_t r0, r1, r2, r3;
                ldmx4(sbB + (bRow + nt * 16) * ROWB + ks * 32 + bCol, r0, r1, r2, r3);
                b[nt * 2][0] = r0; b[nt * 2][1] = r1;
                b[nt * 2 + 1][0] = r2; b[nt * 2 + 1][1] = r3;
            }
#pragma unroll
            for (int mt = 0; mt < 2; mt++)
#pragma unroll
                for (int nt = 0; nt < 8; nt++)
                    mma16816(acc[mt][nt], a[mt][0], a[mt][1], a[mt][2], a[mt][3],
                             b[nt][0], b[nt][1]);
        }
    }

#pragma unroll
    for (int mt = 0; mt < 2; mt++) {
        const int row0 = rowBase + wm * 32 + mt * 16 + lane / 4;
#pragma unroll
        for (int nt = 0; nt < 8; nt++) {
            const int col = colBase + wn * 64 + nt * 8 + (lane & 3) * 2;
            float2* p0 = (float2*)&C[(size_t)row0 * N + col];
            float2* p1 = (float2*)&C[(size_t)(row0 + 8) * N + col];
            *p0 = make_float2(acc[mt][nt][0], acc[mt][nt][1]);
            *p1 = make_float2(acc[mt][nt][2], acc[mt][nt][3]);
        }
    }
}

// ---------------------------------------------------------------------------
// RMSNorm + RoPE; writes split-bf16 q (pre-scaled by 1/sqrt(D)) and k.
// ---------------------------------------------------------------------------
__global__ void __launch_bounds__(128) norm_rope(
    const float* __restrict__ qw, const float* __restrict__ kw) {
    const int m = blockIdx.x >> 4;
    const int h = blockIdx.x & 15;
    const int s = m & (S_ - 1);
    const int d = threadIdx.x;

    const size_t base = (size_t)m * NQKV_ + (size_t)h * D_ + d;
    float qv = g_qkv[base];
    float kv = g_qkv[base + HD_];

    float sq = qv * qv, sk = kv * kv;
#pragma unroll
    for (int off = 16; off > 0; off >>= 1) {
        sq += __shfl_xor_sync(0xffffffffu, sq, off);
        sk += __shfl_xor_sync(0xffffffffu, sk, off);
    }
    __shared__ float wq[4], wk[4];
    __shared__ float shq[128], shk[128];
    const int lane = d & 31, w = d >> 5;
    if (lane == 0) { wq[w] = sq; wk[w] = sk; }
    __syncthreads();
    float tq = wq[0] + wq[1] + wq[2] + wq[3];
    float tk = wk[0] + wk[1] + wk[2] + wk[3];
    float rq = rsqrtf(tq * (1.0f / 128.0f) + 0.01f);
    float rk = rsqrtf(tk * (1.0f / 128.0f) + 0.01f);
    shq[d] = qv * rq * qw[d];
    shk[d] = kv * rk * kw[d];
    __syncthreads();

    const int i2 = d & 63;
    float inv = powf(10000.0f, -(float)(2 * i2) * (1.0f / 128.0f));
    float ang = (float)s * inv;
    float sn, cs;
    sincosf(ang, &sn, &cs);
    float rotq = (d < 64) ? -shq[d + 64] : shq[d - 64];
    float rotk = (d < 64) ? -shk[d + 64] : shk[d - 64];

    float qf = (shq[d] * cs + rotq * sn) * 0.08838834764831845f; // fold 1/sqrt(D)
    float kf = shk[d] * cs + rotk * sn;

    const size_t ob = (size_t)m * HD_ + (size_t)h * D_ + d;
    __nv_bfloat16 qh = __float2bfloat16(qf);
    __nv_bfloat16 kh = __float2bfloat16(kf);
    g_qhi[ob] = qh;
    g_qlo[ob] = __float2bfloat16(qf - __bfloat162float(qh));
    g_khi[ob] = kh;
    g_klo[ob] = __float2bfloat16(kf - __bfloat162float(kh));
}

// ---------------------------------------------------------------------------
// HMMA flash attention: BR=128, BC=64, 8 warps, split-bf16 3-term emulation.
// P kept in registers (S accumulator fragment == A fragment for PV).
// Epilogue writes output directly in [hi|lo|hi] split layout (g_as).
// ---------------------------------------------------------------------------
#define FROWB 272                          // 256B data + 16B pad
#define FQ_BYTES (128 * FROWB)             // 34816 per matrix
#define FKV_BYTES (64 * FROWB)             // 17408 per matrix
#define FSTAGE (4 * FKV_BYTES)             // Khi,Klo,Vhi,Vlo = 69632
#define FLASH_SMEM (2 * FQ_BYTES + 2 * FSTAGE) // 208896

__global__ void __launch_bounds__(256, 1) flash_mma() {
    extern __shared__ char smc[];
    const uint32_t sb = smem_u32(smc);
    const uint32_t sQh = sb, sQl = sb + FQ_BYTES;
    const uint32_t sKV = sb + 2 * FQ_BYTES;

    const int tid = threadIdx.x;
    const int wid = tid >> 5;
    const int lane = tid & 31;
    const int bh = blockIdx.y;
    const int b = bh >> 4;
    const int h = bh & 15;
    const int iTile = (gridDim.x - 1) - blockIdx.x;  // big tiles first
    const int rowBase = iTile * 128;
    const int numIters = 2 * iTile + 2;
    const int g = lane >> 2;   // row within 8
    const int t = lane & 3;    // col pair

    // ---- async loads ----
    // Q: 128 rows x 16 chunks x 2 matrices = 4096 cp16
    {
#pragma unroll
        for (int it = 0; it < 16; it++) {
            int i = tid + it * 256;
            int mat = i >> 11;
            int r = (i >> 4) & 127;
            int c = i & 15;
            const __nv_bfloat16* src =
                (mat ? g_qlo : g_qhi) +
                (size_t)(b * S_ + rowBase + r) * HD_ + h * D_ + c * 8;
            cp16((mat ? sQl : sQh) + r * FROWB + c * 16, src);
        }
        cp_commit();
    }
    auto load_kv = [&](int jt, int stage) {
        const uint32_t st = sKV + stage * FSTAGE;
#pragma unroll
        for (int it = 0; it < 16; it++) {
            int i = tid + it * 256;
            int mat = i >> 10;            // 0:Khi 1:Klo 2:Vhi 3:Vlo
            int r = (i >> 4) & 63;
            int c = i & 15;
            const __nv_bfloat16* src =
                (mat == 0 ? g_khi : mat == 1 ? g_klo : mat == 2 ? g_vhi : g_vlo) +
                (size_t)(b * S_ + jt * 64 + r) * HD_ + h * D_ + c * 8;
            cp16(st + mat * FKV_BYTES + r * FROWB + c * 16, src);
        }
        cp_commit();
    };
    load_kv(0, 0);
    load_kv(1, 1);

    // ---- state ----
    float o[16][4];
#pragma unroll
    for (int nt = 0; nt < 16; nt++)
#pragma unroll
        for (int q = 0; q < 4; q++) o[nt][q] = 0.0f;
    float m_i[2] = {-1e30f, -1e30f};
    float l_i[2] = {0.0f, 0.0f};

    const int warpRow0 = rowBase + wid * 16;
    // ldmatrix lane addressing
    const uint32_t qOff = (uint32_t)((wid * 16 + (lane & 15)) * FROWB + (lane >> 4) * 16);
    const uint32_t kRow = (uint32_t)((lane & 7) + ((lane >> 4) & 1) * 8);
    const uint32_t kColB = (uint32_t)(((lane >> 3) & 1) * 16);
    const uint32_t vRow = (uint32_t)((lane & 7) + ((lane >> 3) & 1) * 8);
    const uint32_t vColB = (uint32_t)(((lane >> 4) & 1) * 16);

    for (int jt = 0; jt < numIters; jt++) {
        if (jt + 1 < numIters) cp_wait<1>(); else cp_wait<0>();
        __syncthreads();

        const int jBase = jt * 64;
        const bool active = (jBase <= warpRow0 + 15);
        if (active) {
            const uint32_t st = sKV + (jt & 1) * FSTAGE;
            const uint32_t Kh = st, Kl = st + FKV_BYTES;
            const uint32_t Vh = st + 2 * FKV_BYTES, Vl = st + 3 * FKV_BYTES;

            // ---- S = Q K^T (3-term split) ----
            float s[8][4];
#pragma unroll
            for (int nt = 0; nt < 8; nt++)
#pragma unroll
                for (int q = 0; q < 4; q++) s[nt][q] = 0.0f;

#pragma unroll
            for (int kt = 0; kt < 8; kt++) {
                uint32_t ah0, ah1, ah2, ah3, al0, al1, al2, al3;
                ldmx4(sQh + qOff + kt * 32, ah0, ah1, ah2, ah3);
                ldmx4(sQl + qOff + kt * 32, al0, al1, al2, al3);
#pragma unroll
                for (int ntp = 0; ntp < 4; ntp++) {
                    uint32_t bh0, bh1, bh2, bh3, bl0, bl1, bl2, bl3;
                    uint32_t ko = (ntp * 16 + kRow) * FROWB + kt * 32 + kColB;
                    ldmx4(Kh + ko, bh0, bh1, bh2, bh3);
                    ldmx4(Kl + ko, bl0, bl1, bl2, bl3);
                    mma16816(s[2 * ntp], ah0, ah1, ah2, ah3, bh0, bh1);
                    mma16816(s[2 * ntp], al0, al1, al2, al3, bh0, bh1);
                    mma16816(s[2 * ntp], ah0, ah1, ah2, ah3, bl0, bl1);
                    mma16816(s[2 * ntp + 1], ah0, ah1, ah2, ah3, bh2, bh3);
                    mma16816(s[2 * ntp + 1], al0, al1, al2, al3, bh2, bh3);
                    mma16816(s[2 * ntp + 1], ah0, ah1, ah2, ah3, bl2, bl3);
                }
            }

            // ---- causal mask ----
            if (jBase + 63 > warpRow0) {
#pragma unroll
                for (int nt = 0; nt < 8; nt++) {
                    int col = jBase + nt * 8 + 2 * t;
                    int r0 = warpRow0 + g, r1 = warpRow0 + g + 8;
                    if (col > r0) s[nt][0] = -1e30f;
                    if (col + 1 > r0) s[nt][1] = -1e30f;
                    if (col > r1) s[nt][2] = -1e30f;
                    if (col + 1 > r1) s[nt][3] = -1e30f;
                }
            }

            // ---- online softmax (per row-half) ----
#pragma unroll
            for (int h2 = 0; h2 < 2; h2++) {
                float tm = -1e30f;
#pragma unroll
                for (int nt = 0; nt < 8; nt++)
                    tm = fmaxf(tm, fmaxf(s[nt][2 * h2], s[nt][2 * h2 + 1]));
                tm = fmaxf(tm, __shfl_xor_sync(0xffffffffu, tm, 1));
                tm = fmaxf(tm, __shfl_xor_sync(0xffffffffu, tm, 2));
                float mnew = fmaxf(m_i[h2], tm);
                float rs = 0.0f;
#pragma unroll
                for (int nt = 0; nt < 8; nt++) {
                    float p0 = __expf(s[nt][2 * h2] - mnew);
                    float p1 = __expf(s[nt][2 * h2 + 1] - mnew);
                    s[nt][2 * h2] = p0;
                    s[nt][2 * h2 + 1] = p1;
                    rs += p0 + p1;
                }
                rs += __shfl_xor_sync(0xffffffffu, rs, 1);
                rs += __shfl_xor_sync(0xffffffffu, rs, 2);
                float alpha = __expf(m_i[h2] - mnew);
                m_i[h2] = mnew;
                l_i[h2] = l_i[h2] * alpha + rs;
#pragma unroll
                for (int nt = 0; nt < 16; nt++) {
                    o[nt][2 * h2] *= alpha;
                    o[nt][2 * h2 + 1] *= alpha;
                }
            }

            // ---- O += P V (3-term split, P packed in-register) ----
#pragma unroll
            for (int kk = 0; kk < 4; kk++) {
                uint32_t ph0, ph1, ph2, ph3, pl0, pl1, pl2, pl3;
                {
                    __nv_bfloat162 x;
                    x = __floats2bfloat162_rn(s[2 * kk][0], s[2 * kk][1]);
                    ph0 = *(uint32_t*)&x;
                    __nv_bfloat162 y = __floats2bfloat162_rn(
                        s[2 * kk][0] - __low2float(x), s[2 * kk][1] - __high2float(x));
                    pl0 = *(uint32_t*)&y;
                    x = __floats2bfloat162_rn(s[2 * kk][2], s[2 * kk][3]);
                    ph1 = *(uint32_t*)&x;
                    y = __floats2bfloat162_rn(
                        s[2 * kk][2] - __low2float(x), s[2 * kk][3] - __high2float(x));
                    pl1 = *(uint32_t*)&y;
                    x = __floats2bfloat162_rn(s[2 * kk + 1][0], s[2 * kk + 1][1]);
                    ph2 = *(uint32_t*)&x;
                    y = __floats2bfloat162_rn(
                        s[2 * kk + 1][0] - __low2float(x), s[2 * kk + 1][1] - __high2float(x));
                    pl2 = *(uint32_t*)&y;
                    x = __floats2bfloat162_rn(s[2 * kk + 1][2], s[2 * kk + 1][3]);
                    ph3 = *(uint32_t*)&x;
                    y = __floats2bfloat162_rn(
                        s[2 * kk + 1][2] - __low2float(x), s[2 * kk + 1][3] - __high2float(x));
                    pl3 = *(uint32_t*)&y;
                }
#pragma unroll
                for (int np = 0; np < 8; np++) {
                    uint32_t vh0, vh1, vh2, vh3, vl0, vl1, vl2, vl3;
                    uint32_t vo = (kk * 16 + vRow) * FROWB + np * 32 + vColB;
                    ldmx4t(Vh + vo, vh0, vh1, vh2, vh3);
                    ldmx4t(Vl + vo, vl0, vl1, vl2, vl3);
                    mma16816(o[2 * np], ph0, ph1, ph2, ph3, vh0, vh1);
                    mma16816(o[2 * np], pl0, pl1, pl2, pl3, vh0, vh1);
                    mma16816(o[2 * np], ph0, ph1, ph2, ph3, vl0, vl1);
                    mma16816(o[2 * np + 1], ph0, ph1, ph2, ph3, vh2, vh3);
                    mma16816(o[2 * np + 1], pl0, pl1, pl2, pl3, vh2, vh3);
                    mma16816(o[2 * np + 1], ph0, ph1, ph2, ph3, vl2, vl3);
                }
            }
        }

        __syncthreads();
        if (jt + 2 < numIters) load_kv(jt + 2, jt & 1);
    }

    // ---- epilogue: normalize, split to bf16, write [hi|lo|hi] into g_as ----
#pragma unroll
    for (int h2 = 0; h2 < 2; h2++) {
        float linv = 1.0f / l_i[h2];
        size_t mrow = (size_t)(b * S_ + warpRow0 + g + 8 * h2);
#pragma unroll
        for (int nt = 0; nt < 16; nt++) {
            float v0 = o[nt][2 * h2] * linv;
            float v1 = o[nt][2 * h2 + 1] * linv;
            __nv_bfloat162 hi2 = __floats2bfloat162_rn(v0, v1);
            __nv_bfloat162 lo2 = __floats2bfloat162_rn(v0 - __low2float(hi2),
                                                       v1 - __high2float(hi2));
            size_t base = mrow * K3_ + h * D_ + nt * 8 + 2 * t;
            *(__nv_bfloat162*)&g_as[base] = hi2;
            *(__nv_bfloat162*)&g_as[base + HD_] = lo2;
            *(__nv_bfloat162*)&g_as[base + 2 * HD_] = hi2;
        }
    }
}

// ---------------------------------------------------------------------------
// Launcher
// ---------------------------------------------------------------------------
extern "C" void kernel_launch(void* const* d_in, const int* in_sizes, int n_in,
                              void* d_out, int out_size) {
    const float* x = (const float*)d_in[0];      // [B,S,E]
    const float* wqkv = (const float*)d_in[1];   // [E,3HD]
    const float* wproj = (const float*)d_in[2];  // [HD,E]
    const float* qw = (const float*)d_in[3];
    const float* kw = (const float*)d_in[4];
    float* out = (float*)d_out;

    void *p_qkv, *p_as, *p_bs;
    cudaGetSymbolAddress(&p_qkv, g_qkv);
    cudaGetSymbolAddress(&p_as, g_as);
    cudaGetSymbolAddress(&p_bs, g_bs);

    cudaFuncSetAttribute(hgemm_bf16, cudaFuncAttributeMaxDynamicSharedMemorySize,
                         GEMM_SMEM);
    cudaFuncSetAttribute(flash_mma, cudaFuncAttributeMaxDynamicSharedMemorySize,
                         FLASH_SMEM);

    // 1) QKV projection (HMMA split-bf16)
    splitA<<<(M_ * E_) / 1024, 256>>>(x, (__nv_bfloat16*)p_as, E_);
    splitTB<<<dim3(NQKV_ / 32, E_ / 32), dim3(32, 8)>>>(
        wqkv, (__nv_bfloat16*)p_bs, E_, NQKV_);
    hgemm_bf16<<<dim3(NQKV_ / BN, M_ / BM), 256, GEMM_SMEM>>>(
        (const __nv_bfloat16*)p_as, (const __nv_bfloat16*)p_bs,
        (float*)p_qkv, NQKV_, K3_);

    // 2) rmsnorm + rope -> split q/k; split V
    norm_rope<<<M_ * H_, 128>>>(qw, kw);
    splitV<<<(M_ * HD_) / 1024, 256>>>();

    // 3) HMMA flash attention -> writes split [hi|lo|hi] directly
    flash_mma<<<dim3(S_ / 128, B_ * H_), 256, FLASH_SMEM>>>();

    // 4) output projection (HMMA split-bf16)
    splitTB<<<dim3(E_ / 32, HD_ / 32), dim3(32, 8)>>>(
        wproj, (__nv_bfloat16*)p_bs, HD_, E_);
    hgemm_bf16<<<dim3(E_ / BN, M_ / BM), 256, GEMM_SMEM>>>(
        (const __nv_bfloat16*)p_as, (const __nv_bfloat16*)p_bs,
        out, E_, K3_);
}

// round 5
// speedup vs baseline: 3.0144x; 1.1863x over previous
#include <cuda_runtime.h>
#include <cuda_bf16.h>
#include <math.h>
#include <stdint.h>

// Problem dims (fixed by the reference)
#define B_ 4
#define S_ 2048
#define E_ 2048
#define H_ 16
#define D_ 128
#define M_ (B_ * S_)        // 8192 tokens
#define NQKV_ (3 * H_ * D_) // 6144
#define HD_ (H_ * D_)       // 2048

// Scratch (allocation-free rule: __device__ globals)
__device__ float g_qkv[(size_t)M_ * NQKV_];        // fused qkv GEMM output
__device__ __nv_bfloat16 g_ahi[(size_t)M_ * E_];   // GEMM A hi (x-split / attn out)
__device__ __nv_bfloat16 g_alo[(size_t)M_ * E_];
__device__ __nv_bfloat16 g_bhi[(size_t)NQKV_ * E_]; // GEMM B^T hi [N,K]
__device__ __nv_bfloat16 g_blo[(size_t)NQKV_ * E_];
__device__ __nv_bfloat16 g_qhi[(size_t)M_ * HD_];  // q (scaled) hi
__device__ __nv_bfloat16 g_qlo[(size_t)M_ * HD_];
__device__ __nv_bfloat16 g_khi[(size_t)M_ * HD_];
__device__ __nv_bfloat16 g_klo[(size_t)M_ * HD_];
__device__ __nv_bfloat16 g_vhi[(size_t)M_ * HD_];
__device__ __nv_bfloat16 g_vlo[(size_t)M_ * HD_];
__device__ float g_cos[(size_t)S_ * D_];           // RoPE tables
__device__ float g_sin[(size_t)S_ * D_];

// ---------------------------------------------------------------------------
// Helpers
// ---------------------------------------------------------------------------
__device__ __forceinline__ uint32_t smem_u32(const void* p) {
    uint32_t a;
    asm("{ .reg .u64 t; cvta.to.shared.u64 t, %1; cvt.u32.u64 %0, t; }"
        : "=r"(a) : "l"(p));
    return a;
}
__device__ __forceinline__ void cp16(uint32_t s, const void* g) {
    asm volatile("cp.async.cg.shared.global [%0], [%1], 16;\n" :: "r"(s), "l"(g));
}
__device__ __forceinline__ void cp_commit() {
    asm volatile("cp.async.commit_group;\n" ::: "memory");
}
template <int N>
__device__ __forceinline__ void cp_wait() {
    asm volatile("cp.async.wait_group %0;\n" :: "n"(N) : "memory");
}
__device__ __forceinline__ void ldmx4(uint32_t a, uint32_t& r0, uint32_t& r1,
                                      uint32_t& r2, uint32_t& r3) {
    asm volatile("ldmatrix.sync.aligned.m8n8.x4.shared.b16 {%0,%1,%2,%3}, [%4];"
                 : "=r"(r0), "=r"(r1), "=r"(r2), "=r"(r3) : "r"(a));
}
__device__ __forceinline__ void ldmx4t(uint32_t a, uint32_t& r0, uint32_t& r1,
                                       uint32_t& r2, uint32_t& r3) {
    asm volatile("ldmatrix.sync.aligned.m8n8.x4.trans.shared.b16 {%0,%1,%2,%3}, [%4];"
                 : "=r"(r0), "=r"(r1), "=r"(r2), "=r"(r3) : "r"(a));
}
__device__ __forceinline__ void mma16816(float* c, uint32_t a0, uint32_t a1,
                                         uint32_t a2, uint32_t a3, uint32_t b0,
                                         uint32_t b1) {
    asm volatile(
        "mma.sync.aligned.m16n8k16.row.col.f32.bf16.bf16.f32 "
        "{%0,%1,%2,%3}, {%4,%5,%6,%7}, {%8,%9}, {%0,%1,%2,%3};"
        : "+f"(c[0]), "+f"(c[1]), "+f"(c[2]), "+f"(c[3])
        : "r"(a0), "r"(a1), "r"(a2), "r"(a3), "r"(b0), "r"(b1));
}

// ---------------------------------------------------------------------------
// Split kernels: fp32 -> separate hi/lo bf16 operands.
// ---------------------------------------------------------------------------
__global__ void __launch_bounds__(256) splitA(
    const float* __restrict__ X, __nv_bfloat16* __restrict__ Yh,
    __nv_bfloat16* __restrict__ Yl) {
    int i4 = (blockIdx.x * 256 + threadIdx.x) * 4;
    float4 v = *(const float4*)&X[i4];
    float f[4] = {v.x, v.y, v.z, v.w};
    __nv_bfloat16 h[4], l[4];
#pragma unroll
    for (int j = 0; j < 4; j++) {
        h[j] = __float2bfloat16(f[j]);
        l[j] = __float2bfloat16(f[j] - __bfloat162float(h[j]));
    }
    __nv_bfloat162* hp = (__nv_bfloat162*)&Yh[i4];
    __nv_bfloat162* lp = (__nv_bfloat162*)&Yl[i4];
    hp[0] = __halves2bfloat162(h[0], h[1]);
    hp[1] = __halves2bfloat162(h[2], h[3]);
    lp[0] = __halves2bfloat162(l[0], l[1]);
    lp[1] = __halves2bfloat162(l[2], l[3]);
}

// B[K,N] fp32 -> hi/lo [N,K] bf16 (transpose + split)
__global__ void __launch_bounds__(256) splitTB(
    const float* __restrict__ B, __nv_bfloat16* __restrict__ Yh,
    __nv_bfloat16* __restrict__ Yl, int K, int N) {
    __shared__ float t[32][33];
    const int k0 = blockIdx.y * 32, n0 = blockIdx.x * 32;
    const int tx = threadIdx.x, ty = threadIdx.y; // 32 x 8
#pragma unroll
    for (int i = 0; i < 32; i += 8)
        t[ty + i][tx] = B[(size_t)(k0 + ty + i) * N + n0 + tx];
    __syncthreads();
#pragma unroll
    for (int i = 0; i < 32; i += 8) {
        float v = t[tx][ty + i];
        __nv_bfloat16 h = __float2bfloat16(v);
        __nv_bfloat16 l = __float2bfloat16(v - __bfloat162float(h));
        size_t o = (size_t)(n0 + ty + i) * K + k0 + tx;
        Yh[o] = h;
        Yl[o] = l;
    }
}

// ---------------------------------------------------------------------------
// RoPE cos/sin table
// ---------------------------------------------------------------------------
__global__ void __launch_bounds__(128) rope_tab() {
    const int s = blockIdx.x;
    const int d = threadIdx.x;
    const int i2 = d & 63;
    float inv = powf(10000.0f, -(float)(2 * i2) * (1.0f / 128.0f));
    float sn, cs;
    sincosf((float)s * inv, &sn, &cs);
    g_cos[(size_t)s * D_ + d] = cs;
    g_sin[(size_t)s * D_ + d] = sn;
}

// ---------------------------------------------------------------------------
// Separate-operand HMMA GEMM: C[M,N] = A[M,K] * B[K,N] with A,B pre-split
// into hi/lo bf16 (3-term emulation: AhBh + AlBh + AhBl).
// 128x128x32 tiles, 2-stage cp.async, 2 CTA/SM, GROUP_M=8 grid swizzle.
// ---------------------------------------------------------------------------
#define BM 128
#define BN 128
#define BK 32
#define ROWB 80                      // 64B data + 16B pad
#define TILE_B (BM * ROWB)           // 10240
#define STAGE_B (4 * TILE_B)         // Ahi,Alo,Bhi,Blo = 40960
#define GEMM_SMEM (2 * STAGE_B)      // 81920

__global__ void __launch_bounds__(256, 2) hgemm_sep(
    const __nv_bfloat16* __restrict__ Ah, const __nv_bfloat16* __restrict__ Al,
    const __nv_bfloat16* __restrict__ Bh, const __nv_bfloat16* __restrict__ Bl,
    float* __restrict__ C, int N, int K) {
    extern __shared__ char smem[];
    const uint32_t sb = smem_u32(smem);
    const int tid = threadIdx.x;
    const int wid = tid >> 5;
    const int lane = tid & 31;
    const int wm = wid & 3;
    const int wn = wid >> 2;
    const int NC = K / BK;

    // GROUP_M=8 swizzle (M/BM = 64, divisible by 8)
    const int nbx = N / BN;
    const int width = 8 * nbx;
    const int group = blockIdx.x / width;
    const int ig = blockIdx.x % width;
    const int rowBase = (group * 8 + (ig & 7)) * BM;
    const int colBase = (ig >> 3) * BN;

    const int lr = tid >> 2;
    const int lcb = (tid & 3) * 16;
    const int lce = (tid & 3) * 8;

    auto load_chunk = [&](int ck, int stg) {
        const int k0 = ck * BK;
        const uint32_t st = sb + stg * STAGE_B;
#pragma unroll
        for (int t = 0; t < 4; t++) {
            const __nv_bfloat16* base = (t == 0) ? Ah : (t == 1) ? Al
                                        : (t == 2) ? Bh : Bl;
            const int gr0 = (t < 2) ? rowBase : colBase;
#pragma unroll
            for (int rr = 0; rr < 2; rr++) {
                int r = lr + rr * 64;
                cp16(st + t * TILE_B + r * ROWB + lcb,
                     base + (size_t)(gr0 + r) * K + k0 + lce);
            }
        }
        cp_commit();
    };

    load_chunk(0, 0);
    load_chunk(1, 1);

    float acc[2][8][4];
#pragma unroll
    for (int i = 0; i < 2; i++)
#pragma unroll
        for (int j = 0; j < 8; j++)
#pragma unroll
            for (int q = 0; q < 4; q++) acc[i][j][q] = 0.0f;

    const uint32_t aOff0 = (uint32_t)((wm * 32 + (lane & 15)) * ROWB + (lane >> 4) * 16);
    const uint32_t bRow = (uint32_t)(wn * 64 + (lane & 7) + ((lane >> 4) & 1) * 8);
    const uint32_t bColB = (uint32_t)(((lane >> 3) & 1) * 16);

    for (int ck = 0; ck < NC; ck++) {
        if (ck == NC - 1) cp_wait<0>(); else cp_wait<1>();
        __syncthreads();

        const uint32_t st = sb + (ck & 1) * STAGE_B;
        const uint32_t sAh = st, sAl = st + TILE_B;
        const uint32_t sBh = st + 2 * TILE_B, sBl = st + 3 * TILE_B;

#pragma unroll
        for (int ks = 0; ks < 2; ks++) {
            uint32_t ah[2][4], al[2][4];
#pragma unroll
            for (int mt = 0; mt < 2; mt++) {
                ldmx4(sAh + aOff0 + mt * 16 * ROWB + ks * 32,
                      ah[mt][0], ah[mt][1], ah[mt][2], ah[mt][3]);
                ldmx4(sAl + aOff0 + mt * 16 * ROWB + ks * 32,
                      al[mt][0], al[mt][1], al[mt][2], al[mt][3]);
            }
#pragma unroll
            for (int ntp = 0; ntp < 4; ntp++) {
                const uint32_t ko = (ntp * 16 + bRow) * ROWB + ks * 32 + bColB;
                uint32_t b0, b1, b2, b3;
                ldmx4(sBh + ko, b0, b1, b2, b3);
#pragma unroll
                for (int mt = 0; mt < 2; mt++) {
                    mma16816(acc[mt][2 * ntp], ah[mt][0], ah[mt][1], ah[mt][2], ah[mt][3], b0, b1);
                    mma16816(acc[mt][2 * ntp], al[mt][0], al[mt][1], al[mt][2], al[mt][3], b0, b1);
                    mma16816(acc[mt][2 * ntp + 1], ah[mt][0], ah[mt][1], ah[mt][2], ah[mt][3], b2, b3);
                    mma16816(acc[mt][2 * ntp + 1], al[mt][0], al[mt][1], al[mt][2], al[mt][3], b2, b3);
                }
                ldmx4(sBl + ko, b0, b1, b2, b3);
#pragma unroll
                for (int mt = 0; mt < 2; mt++) {
                    mma16816(acc[mt][2 * ntp], ah[mt][0], ah[mt][1], ah[mt][2], ah[mt][3], b0, b1);
                    mma16816(acc[mt][2 * ntp + 1], ah[mt][0], ah[mt][1], ah[mt][2], ah[mt][3], b2, b3);
                }
            }
        }
        __syncthreads();
        if (ck + 2 < NC) load_chunk(ck + 2, ck & 1);
    }

#pragma unroll
    for (int mt = 0; mt < 2; mt++) {
        const int row0 = rowBase + wm * 32 + mt * 16 + lane / 4;
#pragma unroll
        for (int nt = 0; nt < 8; nt++) {
            const int col = colBase + wn * 64 + nt * 8 + (lane & 3) * 2;
            float2* p0 = (float2*)&C[(size_t)row0 * N + col];
            float2* p1 = (float2*)&C[(size_t)(row0 + 8) * N + col];
            *p0 = make_float2(acc[mt][nt][0], acc[mt][nt][1]);
            *p1 = make_float2(acc[mt][nt][2], acc[mt][nt][3]);
        }
    }
}

// ---------------------------------------------------------------------------
// RMSNorm + RoPE (table) -> split q/k; also splits V. One block per (m,h).
// ---------------------------------------------------------------------------
__global__ void __launch_bounds__(128) norm_rope(
    const float* __restrict__ qw, const float* __restrict__ kw) {
    const int m = blockIdx.x >> 4;
    const int h = blockIdx.x & 15;
    const int s = m & (S_ - 1);
    const int d = threadIdx.x;

    const size_t base = (size_t)m * NQKV_ + (size_t)h * D_ + d;
    float qv = g_qkv[base];
    float kv = g_qkv[base + HD_];
    float vv = g_qkv[base + 2 * HD_];

    float sq = qv * qv, sk = kv * kv;
#pragma unroll
    for (int off = 16; off > 0; off >>= 1) {
        sq += __shfl_xor_sync(0xffffffffu, sq, off);
        sk += __shfl_xor_sync(0xffffffffu, sk, off);
    }
    __shared__ float wq[4], wk[4];
    __shared__ float shq[128], shk[128];
    const int lane = d & 31, w = d >> 5;
    if (lane == 0) { wq[w] = sq; wk[w] = sk; }
    __syncthreads();
    float tq = wq[0] + wq[1] + wq[2] + wq[3];
    float tk = wk[0] + wk[1] + wk[2] + wk[3];
    float rq = rsqrtf(tq * (1.0f / 128.0f) + 0.01f);
    float rk = rsqrtf(tk * (1.0f / 128.0f) + 0.01f);
    shq[d] = qv * rq * qw[d];
    shk[d] = kv * rk * kw[d];
    __syncthreads();

    float cs = g_cos[(size_t)s * D_ + d];
    float sn = g_sin[(size_t)s * D_ + d];
    float rotq = (d < 64) ? -shq[d + 64] : shq[d - 64];
    float rotk = (d < 64) ? -shk[d + 64] : shk[d - 64];

    float qf = (shq[d] * cs + rotq * sn) * 0.08838834764831845f; // fold 1/sqrt(D)
    float kf = shk[d] * cs + rotk * sn;

    const size_t ob = (size_t)m * HD_ + (size_t)h * D_ + d;
    __nv_bfloat16 qh = __float2bfloat16(qf);
    __nv_bfloat16 kh = __float2bfloat16(kf);
    __nv_bfloat16 vh = __float2bfloat16(vv);
    g_qhi[ob] = qh;
    g_qlo[ob] = __float2bfloat16(qf - __bfloat162float(qh));
    g_khi[ob] = kh;
    g_klo[ob] = __float2bfloat16(kf - __bfloat162float(kh));
    g_vhi[ob] = vh;
    g_vlo[ob] = __float2bfloat16(vv - __bfloat162float(vh));
}

// ---------------------------------------------------------------------------
// HMMA flash attention: BR=128, BC=64, 8 warps, split-bf16 3-term emulation.
// Epilogue writes hi/lo output directly (consumed by out-proj GEMM).
// ---------------------------------------------------------------------------
#define FROWB 272                          // 256B data + 16B pad
#define FQ_BYTES (128 * FROWB)
#define FKV_BYTES (64 * FROWB)
#define FSTAGE (4 * FKV_BYTES)
#define FLASH_SMEM (2 * FQ_BYTES + 2 * FSTAGE)

__global__ void __launch_bounds__(256, 1) flash_mma() {
    extern __shared__ char smc[];
    const uint32_t sb = smem_u32(smc);
    const uint32_t sQh = sb, sQl = sb + FQ_BYTES;
    const uint32_t sKV = sb + 2 * FQ_BYTES;

    const int tid = threadIdx.x;
    const int wid = tid >> 5;
    const int lane = tid & 31;
    const int bh = blockIdx.y;
    const int b = bh >> 4;
    const int h = bh & 15;
    const int iTile = (gridDim.x - 1) - blockIdx.x;
    const int rowBase = iTile * 128;
    const int numIters = 2 * iTile + 2;
    const int g = lane >> 2;
    const int t = lane & 3;

    {
#pragma unroll
        for (int it = 0; it < 16; it++) {
            int i = tid + it * 256;
            int mat = i >> 11;
            int r = (i >> 4) & 127;
            int c = i & 15;
            const __nv_bfloat16* src =
                (mat ? g_qlo : g_qhi) +
                (size_t)(b * S_ + rowBase + r) * HD_ + h * D_ + c * 8;
            cp16((mat ? sQl : sQh) + r * FROWB + c * 16, src);
        }
        cp_commit();
    }
    auto load_kv = [&](int jt, int stage) {
        const uint32_t st = sKV + stage * FSTAGE;
#pragma unroll
        for (int it = 0; it < 16; it++) {
            int i = tid + it * 256;
            int mat = i >> 10;
            int r = (i >> 4) & 63;
            int c = i & 15;
            const __nv_bfloat16* src =
                (mat == 0 ? g_khi : mat == 1 ? g_klo : mat == 2 ? g_vhi : g_vlo) +
                (size_t)(b * S_ + jt * 64 + r) * HD_ + h * D_ + c * 8;
            cp16(st + mat * FKV_BYTES + r * FROWB + c * 16, src);
        }
        cp_commit();
    };
    load_kv(0, 0);
    load_kv(1, 1);

    float o[16][4];
#pragma unroll
    for (int nt = 0; nt < 16; nt++)
#pragma unroll
        for (int q = 0; q < 4; q++) o[nt][q] = 0.0f;
    float m_i[2] = {-1e30f, -1e30f};
    float l_i[2] = {0.0f, 0.0f};

    const int warpRow0 = rowBase + wid * 16;
    const uint32_t qOff = (uint32_t)((wid * 16 + (lane & 15)) * FROWB + (lane >> 4) * 16);
    const uint32_t kRow = (uint32_t)((lane & 7) + ((lane >> 4) & 1) * 8);
    const uint32_t kColB = (uint32_t)(((lane >> 3) & 1) * 16);
    const uint32_t vRow = (uint32_t)((lane & 7) + ((lane >> 3) & 1) * 8);
    const uint32_t vColB = (uint32_t)(((lane >> 4) & 1) * 16);

    for (int jt = 0; jt < numIters; jt++) {
        if (jt + 1 < numIters) cp_wait<1>(); else cp_wait<0>();
        __syncthreads();

        const int jBase = jt * 64;
        const bool active = (jBase <= warpRow0 + 15);
        if (active) {
            const uint32_t st = sKV + (jt & 1) * FSTAGE;
            const uint32_t Kh = st, Kl = st + FKV_BYTES;
            const uint32_t Vh = st + 2 * FKV_BYTES, Vl = st + 3 * FKV_BYTES;

            float s[8][4];
#pragma unroll
            for (int nt = 0; nt < 8; nt++)
#pragma unroll
                for (int q = 0; q < 4; q++) s[nt][q] = 0.0f;

#pragma unroll
            for (int kt = 0; kt < 8; kt++) {
                uint32_t ah0, ah1, ah2, ah3, al0, al1, al2, al3;
                ldmx4(sQh + qOff + kt * 32, ah0, ah1, ah2, ah3);
                ldmx4(sQl + qOff + kt * 32, al0, al1, al2, al3);
#pragma unroll
                for (int ntp = 0; ntp < 4; ntp++) {
                    uint32_t bh0, bh1, bh2, bh3, bl0, bl1, bl2, bl3;
                    uint32_t ko = (ntp * 16 + kRow) * FROWB + kt * 32 + kColB;
                    ldmx4(Kh + ko, bh0, bh1, bh2, bh3);
                    ldmx4(Kl + ko, bl0, bl1, bl2, bl3);
                    mma16816(s[2 * ntp], ah0, ah1, ah2, ah3, bh0, bh1);
                    mma16816(s[2 * ntp], al0, al1, al2, al3, bh0, bh1);
                    mma16816(s[2 * ntp], ah0, ah1, ah2, ah3, bl0, bl1);
                    mma16816(s[2 * ntp + 1], ah0, ah1, ah2, ah3, bh2, bh3);
                    mma16816(s[2 * ntp + 1], al0, al1, al2, al3, bh2, bh3);
                    mma16816(s[2 * ntp + 1], ah0, ah1, ah2, ah3, bl2, bl3);
                }
            }

            if (jBase + 63 > warpRow0) {
#pragma unroll
                for (int nt = 0; nt < 8; nt++) {
                    int col = jBase + nt * 8 + 2 * t;
                    int r0 = warpRow0 + g, r1 = warpRow0 + g + 8;
                    if (col > r0) s[nt][0] = -1e30f;
                    if (col + 1 > r0) s[nt][1] = -1e30f;
                    if (col > r1) s[nt][2] = -1e30f;
                    if (col + 1 > r1) s[nt][3] = -1e30f;
                }
            }

#pragma unroll
            for (int h2 = 0; h2 < 2; h2++) {
                float tm = -1e30f;
#pragma unroll
                for (int nt = 0; nt < 8; nt++)
                    tm = fmaxf(tm, fmaxf(s[nt][2 * h2], s[nt][2 * h2 + 1]));
                tm = fmaxf(tm, __shfl_xor_sync(0xffffffffu, tm, 1));
                tm = fmaxf(tm, __shfl_xor_sync(0xffffffffu, tm, 2));
                float mnew = fmaxf(m_i[h2], tm);
                float rs = 0.0f;
#pragma unroll
                for (int nt = 0; nt < 8; nt++) {
                    float p0 = __expf(s[nt][2 * h2] - mnew);
                    float p1 = __expf(s[nt][2 * h2 + 1] - mnew);
                    s[nt][2 * h2] = p0;
                    s[nt][2 * h2 + 1] = p1;
                    rs += p0 + p1;
                }
                rs += __shfl_xor_sync(0xffffffffu, rs, 1);
                rs += __shfl_xor_sync(0xffffffffu, rs, 2);
                float alpha = __expf(m_i[h2] - mnew);
                m_i[h2] = mnew;
                l_i[h2] = l_i[h2] * alpha + rs;
#pragma unroll
                for (int nt = 0; nt < 16; nt++) {
                    o[nt][2 * h2] *= alpha;
                    o[nt][2 * h2 + 1] *= alpha;
                }
            }

#pragma unroll
            for (int kk = 0; kk < 4; kk++) {
                uint32_t ph0, ph1, ph2, ph3, pl0, pl1, pl2, pl3;
                {
                    __nv_bfloat162 x, y;
                    x = __floats2bfloat162_rn(s[2 * kk][0], s[2 * kk][1]);
                    ph0 = *(uint32_t*)&x;
                    y = __floats2bfloat162_rn(s[2 * kk][0] - __low2float(x),
                                              s[2 * kk][1] - __high2float(x));
                    pl0 = *(uint32_t*)&y;
                    x = __floats2bfloat162_rn(s[2 * kk][2], s[2 * kk][3]);
                    ph1 = *(uint32_t*)&x;
                    y = __floats2bfloat162_rn(s[2 * kk][2] - __low2float(x),
                                              s[2 * kk][3] - __high2float(x));
                    pl1 = *(uint32_t*)&y;
                    x = __floats2bfloat162_rn(s[2 * kk + 1][0], s[2 * kk + 1][1]);
                    ph2 = *(uint32_t*)&x;
                    y = __floats2bfloat162_rn(s[2 * kk + 1][0] - __low2float(x),
                                              s[2 * kk + 1][1] - __high2float(x));
                    pl2 = *(uint32_t*)&y;
                    x = __floats2bfloat162_rn(s[2 * kk + 1][2], s[2 * kk + 1][3]);
                    ph3 = *(uint32_t*)&x;
                    y = __floats2bfloat162_rn(s[2 * kk + 1][2] - __low2float(x),
                                              s[2 * kk + 1][3] - __high2float(x));
                    pl3 = *(uint32_t*)&y;
                }
#pragma unroll
                for (int np = 0; np < 8; np++) {
                    uint32_t vh0, vh1, vh2, vh3, vl0, vl1, vl2, vl3;
                    uint32_t vo = (kk * 16 + vRow) * FROWB + np * 32 + vColB;
                    ldmx4t(Vh + vo, vh0, vh1, vh2, vh3);
                    ldmx4t(Vl + vo, vl0, vl1, vl2, vl3);
                    mma16816(o[2 * np], ph0, ph1, ph2, ph3, vh0, vh1);
                    mma16816(o[2 * np], pl0, pl1, pl2, pl3, vh0, vh1);
                    mma16816(o[2 * np], ph0, ph1, ph2, ph3, vl0, vl1);
                    mma16816(o[2 * np + 1], ph0, ph1, ph2, ph3, vh2, vh3);
                    mma16816(o[2 * np + 1], pl0, pl1, pl2, pl3, vh2, vh3);
                    mma16816(o[2 * np + 1], ph0, ph1, ph2, ph3, vl2, vl3);
                }
            }
        }

        __syncthreads();
        if (jt + 2 < numIters) load_kv(jt + 2, jt & 1);
    }

    // epilogue: normalize, split to hi/lo bf16 (plain [M, HD] layout)
#pragma unroll
    for (int h2 = 0; h2 < 2; h2++) {
        float linv = 1.0f / l_i[h2];
        size_t mrow = (size_t)(b * S_ + warpRow0 + g + 8 * h2);
#pragma unroll
        for (int nt = 0; nt < 16; nt++) {
            float v0 = o[nt][2 * h2] * linv;
            float v1 = o[nt][2 * h2 + 1] * linv;
            __nv_bfloat162 hi2 = __floats2bfloat162_rn(v0, v1);
            __nv_bfloat162 lo2 = __floats2bfloat162_rn(v0 - __low2float(hi2),
                                                       v1 - __high2float(hi2));
            size_t base = mrow * HD_ + h * D_ + nt * 8 + 2 * t;
            *(__nv_bfloat162*)&g_ahi[base] = hi2;
            *(__nv_bfloat162*)&g_alo[base] = lo2;
        }
    }
}

// ---------------------------------------------------------------------------
// Launcher
// ---------------------------------------------------------------------------
extern "C" void kernel_launch(void* const* d_in, const int* in_sizes, int n_in,
                              void* d_out, int out_size) {
    const float* x = (const float*)d_in[0];      // [B,S,E]
    const float* wqkv = (const float*)d_in[1];   // [E,3HD]
    const float* wproj = (const float*)d_in[2];  // [HD,E]
    const float* qw = (const float*)d_in[3];
    const float* kw = (const float*)d_in[4];
    float* out = (float*)d_out;

    void *p_qkv, *p_ahi, *p_alo, *p_bhi, *p_blo;
    cudaGetSymbolAddress(&p_qkv, g_qkv);
    cudaGetSymbolAddress(&p_ahi, g_ahi);
    cudaGetSymbolAddress(&p_alo, g_alo);
    cudaGetSymbolAddress(&p_bhi, g_bhi);
    cudaGetSymbolAddress(&p_blo, g_blo);

    cudaFuncSetAttribute(hgemm_sep, cudaFuncAttributeMaxDynamicSharedMemorySize,
                         GEMM_SMEM);
    cudaFuncSetAttribute(flash_mma, cudaFuncAttributeMaxDynamicSharedMemorySize,
                         FLASH_SMEM);

    // 0) RoPE tables
    rope_tab<<<S_, 128>>>();

    // 1) QKV projection (HMMA split-bf16, separate operands)
    splitA<<<(M_ * E_) / 1024, 256>>>(x, (__nv_bfloat16*)p_ahi,
                                      (__nv_bfloat16*)p_alo);
    splitTB<<<dim3(NQKV_ / 32, E_ / 32), dim3(32, 8)>>>(
        wqkv, (__nv_bfloat16*)p_bhi, (__nv_bfloat16*)p_blo, E_, NQKV_);
    hgemm_sep<<<(NQKV_ / BN) * (M_ / BM), 256, GEMM_SMEM>>>(
        (const __nv_bfloat16*)p_ahi, (const __nv_bfloat16*)p_alo,
        (const __nv_bfloat16*)p_bhi, (const __nv_bfloat16*)p_blo,
        (float*)p_qkv, NQKV_, E_);

    // 2) rmsnorm + rope + v-split
    norm_rope<<<M_ * H_, 128>>>(qw, kw);

    // 3) HMMA flash attention -> writes hi/lo output
    flash_mma<<<dim3(S_ / 128, B_ * H_), 256, FLASH_SMEM>>>();

    // 4) output projection
    splitTB<<<dim3(E_ / 32, HD_ / 32), dim3(32, 8)>>>(
        wproj, (__nv_bfloat16*)p_bhi, (__nv_bfloat16*)p_blo, HD_, E_);
    hgemm_sep<<<(E_ / BN) * (M_ / BM), 256, GEMM_SMEM>>>(
        (const __nv_bfloat16*)p_ahi, (const __nv_bfloat16*)p_alo,
        (const __nv_bfloat16*)p_bhi, (const __nv_bfloat16*)p_blo,
        out, E_, HD_);
}